// round 11
// baseline (speedup 1.0000x reference)
#include <cuda_runtime.h>

#define NCAM 6
#define NCLS 10
#define NBKT (NCAM * NCLS)
#define NMAX 4096
#define MMAX 8192
#define CAP  192         // per-bucket padded capacity (~102 expected, 9-sigma headroom)
#define IMGW 1600
#define IMGH 900
#define NBLK 148
#define NTHR 512
#define MAXSL 16

// ---- device scratch (static; no allocs) ----
__device__ float4 g_proj  [NCAM * NMAX];
__device__ float  g_parea [NCAM * NMAX];
__device__ float  g_validf[NCAM * NMAX];
__device__ int    g_vlist [NCAM * NMAX];
__device__ int    g_vcount[NCAM];
__device__ int    g_brank [NBKT];            // per-bucket det counts (atomic ranks)
__device__ float4 g_det   [NBKT * CAP * 2];  // interleaved: [2i]=box, [2i+1]=(area,score,-,-)
__device__ float  g_probs [NCLS * NMAX];     // class-major accumulators
__device__ unsigned          g_bar_count;    // static zero-init; self-resetting
__device__ volatile unsigned g_bar_epoch;    // grows monotonically across replays

// ---- software grid barrier (R5/R10-proven; all NBLK blocks co-resident) ----
__device__ __forceinline__ void grid_barrier(unsigned start, unsigned k) {
    __syncthreads();
    if (threadIdx.x == 0) {
        __threadfence();
        unsigned a = atomicAdd(&g_bar_count, 1u);
        if (a == (unsigned)gridDim.x - 1u) {
            atomicExch(&g_bar_count, 0u);
            __threadfence();
            atomicAdd((unsigned*)&g_bar_epoch, 1u);
        } else {
            while (g_bar_epoch - start < k) __nanosleep(32);
        }
        __threadfence();
    }
    __syncthreads();
}

__global__ __launch_bounds__(NTHR)
void fused_kernel(const float* __restrict__ boxes,
                  const float* __restrict__ iam,    // (1,6,4,4)
                  const float* __restrict__ lam,    // (1,4,4)
                  const float* __restrict__ l2i,    // (1,6,4,4)
                  const float* __restrict__ dbox,
                  const int*   __restrict__ dlab,
                  const float* __restrict__ dsc,
                  const int*   __restrict__ dbat,
                  const int*   __restrict__ dcam,
                  float* __restrict__ out,
                  int N, int M) {
    const int gtid = blockIdx.x * NTHR + threadIdx.x;
    const int T    = gridDim.x * NTHR;

    __shared__ unsigned s_start;
    __shared__ int s_cnt[NBKT];
    __shared__ int s_vc[NCAM];
    __shared__ int s_vbase[NCAM + 1];
    __shared__ int s_SL;

    if (threadIdx.x == 0) s_start = g_bar_epoch;   // quiescent before first arrive
    __syncthreads();
    const unsigned start = s_start;

    // ========== Phase A: projection(+vlist) | padded scatter | zero-probs ===
    {
        const int TOTA = NCAM * N + M + NCLS * NMAX;
        for (int w = gtid; w < TOTA; w += T) {
            if (w < NCAM * N) {
                int cam = w / N;
                int n   = w - cam * N;
                const float* bp = boxes + n * 7;
                float bx = bp[0], by = bp[1], bz = bp[2];
                float ddx = bp[3], ddy = bp[4], ddz = bp[5];
                float yaw = bp[6];
                float sn, cs;
                sincosf(yaw, &sn, &cs);

                float r00=lam[0], r01=lam[1], r02=lam[2],  t0=lam[3];
                float r10=lam[4], r11=lam[5], r12=lam[6],  t1=lam[7];
                float r20=lam[8], r21=lam[9], r22=lam[10], t2=lam[11];
                float A = r11*r22 - r12*r21;
                float B = r02*r21 - r01*r22;
                float C = r01*r12 - r02*r11;
                float D = r12*r20 - r10*r22;
                float E = r00*r22 - r02*r20;
                float F = r02*r10 - r00*r12;
                float G = r10*r21 - r11*r20;
                float H = r01*r20 - r00*r21;
                float I = r00*r11 - r01*r10;
                float det = r00*A + r01*D + r02*G;
                float id  = __fdiv_rn(1.0f, det);
                float i00=A*id, i01=B*id, i02=C*id;
                float i10=D*id, i11=E*id, i12=F*id;
                float i20=G*id, i21=H*id, i22=I*id;

                const float* L  = l2i + cam * 16;
                const float* Ai = iam + cam * 16;
                int mnx =  0x7fffffff, mny =  0x7fffffff;
                int mxx = -0x7fffffff-1, mxy = -0x7fffffff-1;
                #pragma unroll
                for (int k = 0; k < 8; k++) {
                    float lx = ((k & 1) ? 0.5f : -0.5f) * ddx;
                    float ly = ((k & 2) ? 0.5f : -0.5f) * ddy;
                    float lz = ((k & 4) ? 0.5f : -0.5f) * ddz;
                    float wx = lx*cs - ly*sn + bx;
                    float wy = lx*sn + ly*cs + by;
                    float wz = lz + bz;
                    float ax = wx - t0, ay = wy - t1, az = wz - t2;
                    float px = i00*ax + i01*ay + i02*az;
                    float py = i10*ax + i11*ay + i12*az;
                    float pz = i20*ax + i21*ay + i22*az;

                    float cx  = L[0]*px + L[1]*py + L[2]*pz  + L[3];
                    float cyv = L[4]*px + L[5]*py + L[6]*pz  + L[7];
                    float cz  = L[8]*px + L[9]*py + L[10]*pz + L[11];
                    float z = fminf(fmaxf(cz, 1e-5f), 100000.0f);
                    float x = __fdiv_rn(cx, z);     // IEEE truncation boundaries
                    float y = __fdiv_rn(cyv, z);
                    float ux = Ai[0]*x + Ai[1]*y + Ai[2]*z + Ai[3];
                    float uy = Ai[4]*x + Ai[5]*y + Ai[6]*z + Ai[7];
                    int ixi = (int)ux;  ixi = min(max(ixi, 0), IMGW);  // cvt.rzi
                    int iyi = (int)uy;  iyi = min(max(iyi, 0), IMGH);
                    mnx = min(mnx, ixi); mxx = max(mxx, ixi);
                    mny = min(mny, iyi); mxy = max(mxy, iyi);
                }
                float fx1 = (float)mnx, fy1 = (float)mny;
                float fx2 = (float)mxx, fy2 = (float)mxy;
                bool valid = (mxx - mnx) > 0 && (mxy - mny) > 0;
                g_proj  [cam*N + n] = make_float4(fx1, fy1, fx2, fy2);
                g_parea [cam*N + n] = (fx2 - fx1) * (fy2 - fy1);
                g_validf[cam*N + n] = valid ? 1.0f : 0.0f;
                if (valid) {
                    int pos = atomicAdd(&g_vcount[cam], 1);   // order irrelevant
                    g_vlist[cam*N + pos] = n;
                }
            } else if (w < NCAM * N + M) {
                int m = w - NCAM * N;
                int l = dlab[m], b = dbat[m], c = dcam[m];
                if (b == 0 && l >= 1 && l <= NCLS && c >= 0 && c < NCAM) {
                    int bkt = c * NCLS + l - 1;
                    int r = atomicAdd(&g_brank[bkt], 1);
                    if (r < CAP) {               // memory-safety clamp (~102/bkt expected)
                        float4 db = __ldg((const float4*)dbox + m);
                        int slot = bkt * CAP + r;
                        g_det[2*slot]   = db;
                        g_det[2*slot+1] = make_float4(
                            (db.z - db.x) * (db.w - db.y), dsc[m], 0.0f, 0.0f);
                    }
                }
            } else {
                g_probs[w - NCAM * N - M] = 0.0f;
            }
        }
    }

    grid_barrier(start, 1);

    // ---- block-local: bucket counts, valid bases, slice count --------------
    if (threadIdx.x < NBKT) {
        int c = g_brank[threadIdx.x];
        s_cnt[threadIdx.x] = c < CAP ? c : CAP;
    }
    if (threadIdx.x < NCAM) s_vc[threadIdx.x] = g_vcount[threadIdx.x];
    __syncthreads();
    if (threadIdx.x == 0) {
        int p = 0;
        #pragma unroll
        for (int c = 0; c < NCAM; c++) { s_vbase[c] = p; p += s_vc[c]; }
        s_vbase[NCAM] = p;
        int vt = p > 0 ? p : 1;
        int sl = T / vt;
        if (sl < 1) sl = 1;
        if (sl > MAXSL) sl = MAXSL;
        s_SL = sl;
    }
    __syncthreads();

    // ========== Phase C: main IoU class accumulation ========================
    {
        const int SL   = s_SL;
        const int vtot = s_vbase[NCAM];
        const int W    = vtot * SL;
        for (int w = gtid; w < W; w += T) {
            int sl = w / vtot;            // consecutive threads -> consecutive pairs
            int p  = w - sl * vtot;
            int cam = 0;
            while (p >= s_vbase[cam + 1]) cam++;
            int i  = p - s_vbase[cam];
            int n  = g_vlist[cam*N + i];

            float4 pb = g_proj [cam*N + n];
            float  pa = g_parea[cam*N + n];

            #pragma unroll
            for (int cls = 0; cls < NCLS; cls++) {
                int bkt  = cam*NCLS + cls;
                int len  = s_cnt[bkt];
                int base = bkt * CAP;
                int lo = base + (len * sl)       / SL;
                int hi = base + (len * (sl + 1)) / SL;
                float a = 0.0f;
                #pragma unroll 4
                for (int m = lo; m < hi; m++) {
                    float4 db  = g_det[2*m];       // box: same 128B line as meta
                    float4 as2 = g_det[2*m+1];     // (area, score, -, -)
                    float lx = fmaxf(db.x, pb.x);
                    float ly = fmaxf(db.y, pb.y);
                    float rx = fminf(db.z, pb.z);
                    float ry = fminf(db.w, pb.w);
                    float wx = fmaxf(rx - lx, 0.0f);
                    float wy = fmaxf(ry - ly, 0.0f);
                    float inter = wx * wy;
                    float uni   = as2.x + pa - inter;
                    float iou   = __fdividef(inter, uni);
                    a = fmaf(iou, as2.y, a);
                }
                if (a != 0.0f) atomicAdd(&g_probs[cls * NMAX + n], a);
            }
        }
    }

    grid_barrier(start, 2);

    // ========== Phase D: finalize + counter reset ============================
    for (int n = gtid; n < N; n += T) {
        float vs = 0.0f;
        #pragma unroll
        for (int cam = 0; cam < NCAM; cam++) vs += g_validf[cam*N + n];
        float denom = 1e-5f + vs;
        float best = __fdiv_rn(g_probs[n], denom);
        int bi = 0;
        #pragma unroll
        for (int c = 1; c < NCLS; c++) {
            float mv = __fdiv_rn(g_probs[c * NMAX + n], denom);
            if (mv > best) { best = mv; bi = c; }
        }
        out[n]     = (float)(bi + 1);  // pred_labels
        out[N + n] = best;             // pred_scores
    }

    // restore replay-carried counters for the next graph replay
    if (gtid < NBKT) g_brank[gtid] = 0;
    if (gtid < NCAM) g_vcount[gtid] = 0;
}

// ============================================================================
extern "C" void kernel_launch(void* const* d_in, const int* in_sizes, int n_in,
                              void* d_out, int out_size) {
    const float* boxes = (const float*)d_in[0];
    const float* iam   = (const float*)d_in[1];
    const float* lam   = (const float*)d_in[2];
    const float* l2i   = (const float*)d_in[3];
    const float* dbox  = (const float*)d_in[4];
    const int*   dlab  = (const int*)  d_in[5];
    const float* dsc   = (const float*)d_in[6];
    const int*   dbat  = (const int*)  d_in[7];
    const int*   dcam  = (const int*)  d_in[8];
    int N = in_sizes[0] / 7;
    int M = in_sizes[4] / 4;
    if (N > NMAX) N = NMAX;
    if (M > MMAX) M = MMAX;
    float* out = (float*)d_out;

    fused_kernel<<<NBLK, NTHR>>>(boxes, iam, lam, l2i, dbox, dlab, dsc,
                                 dbat, dcam, out, N, M);
}

// round 12
// speedup vs baseline: 1.0750x; 1.0750x over previous
#include <cuda_runtime.h>

#define NCAM 6
#define NCLS 10
#define NBKT (NCAM * NCLS)
#define NMAX 4096
#define MMAX 8192
#define CAP  192         // per-bucket padded capacity (~102 expected)
#define IMGW 1600
#define IMGH 900
#define MAXSL 32

// ---- device scratch (static; no allocs) ----
__device__ float4 g_proj  [NCAM * NMAX];
__device__ float  g_parea [NCAM * NMAX];
__device__ float  g_validf[NCAM * NMAX];
__device__ int    g_vlist [NCAM * NMAX];
__device__ int    g_vcount[NCAM];
__device__ int    g_brank [NBKT];            // per-bucket det counts (atomic ranks)
__device__ float4 g_sbox  [NBKT * CAP];      // padded bucket storage
__device__ float2 g_sas   [NBKT * CAP];      // (det_area, score)
__device__ float  g_probs [NCLS * NMAX];     // class-major accumulators

// ============================================================================
// K1: projection(+vlist) | padded-bucket scatter | zero-probs  (1 item/thread)
// ============================================================================
__global__ void k1_prep(const float* __restrict__ boxes,
                        const float* __restrict__ iam,
                        const float* __restrict__ lam,
                        const float* __restrict__ l2i,
                        const float* __restrict__ dbox,
                        const int*   __restrict__ dlab,
                        const float* __restrict__ dsc,
                        const int*   __restrict__ dbat,
                        const int*   __restrict__ dcam,
                        int N, int M) {
    int w = blockIdx.x * blockDim.x + threadIdx.x;
    if (w < NCAM * N) {
        int cam = w / N;
        int n   = w - cam * N;
        const float* bp = boxes + n * 7;
        float bx = bp[0], by = bp[1], bz = bp[2];
        float ddx = bp[3], ddy = bp[4], ddz = bp[5];
        float yaw = bp[6];
        float sn, cs;
        sincosf(yaw, &sn, &cs);

        float r00=lam[0], r01=lam[1], r02=lam[2],  t0=lam[3];
        float r10=lam[4], r11=lam[5], r12=lam[6],  t1=lam[7];
        float r20=lam[8], r21=lam[9], r22=lam[10], t2=lam[11];
        float A = r11*r22 - r12*r21;
        float B = r02*r21 - r01*r22;
        float C = r01*r12 - r02*r11;
        float D = r12*r20 - r10*r22;
        float E = r00*r22 - r02*r20;
        float F = r02*r10 - r00*r12;
        float G = r10*r21 - r11*r20;
        float H = r01*r20 - r00*r21;
        float I = r00*r11 - r01*r10;
        float det = r00*A + r01*D + r02*G;
        float id  = __fdiv_rn(1.0f, det);
        float i00=A*id, i01=B*id, i02=C*id;
        float i10=D*id, i11=E*id, i12=F*id;
        float i20=G*id, i21=H*id, i22=I*id;

        const float* L  = l2i + cam * 16;
        const float* Ai = iam + cam * 16;
        int mnx =  0x7fffffff, mny =  0x7fffffff;
        int mxx = -0x7fffffff-1, mxy = -0x7fffffff-1;
        #pragma unroll
        for (int k = 0; k < 8; k++) {
            float lx = ((k & 1) ? 0.5f : -0.5f) * ddx;
            float ly = ((k & 2) ? 0.5f : -0.5f) * ddy;
            float lz = ((k & 4) ? 0.5f : -0.5f) * ddz;
            float wx = lx*cs - ly*sn + bx;
            float wy = lx*sn + ly*cs + by;
            float wz = lz + bz;
            float ax = wx - t0, ay = wy - t1, az = wz - t2;
            float px = i00*ax + i01*ay + i02*az;
            float py = i10*ax + i11*ay + i12*az;
            float pz = i20*ax + i21*ay + i22*az;

            float cx  = L[0]*px + L[1]*py + L[2]*pz  + L[3];
            float cyv = L[4]*px + L[5]*py + L[6]*pz  + L[7];
            float cz  = L[8]*px + L[9]*py + L[10]*pz + L[11];
            float z = fminf(fmaxf(cz, 1e-5f), 100000.0f);
            float x = __fdiv_rn(cx, z);     // IEEE truncation boundaries
            float y = __fdiv_rn(cyv, z);
            float ux = Ai[0]*x + Ai[1]*y + Ai[2]*z + Ai[3];
            float uy = Ai[4]*x + Ai[5]*y + Ai[6]*z + Ai[7];
            int ixi = (int)ux;  ixi = min(max(ixi, 0), IMGW);  // cvt.rzi
            int iyi = (int)uy;  iyi = min(max(iyi, 0), IMGH);
            mnx = min(mnx, ixi); mxx = max(mxx, ixi);
            mny = min(mny, iyi); mxy = max(mxy, iyi);
        }
        float fx1 = (float)mnx, fy1 = (float)mny;
        float fx2 = (float)mxx, fy2 = (float)mxy;
        bool valid = (mxx - mnx) > 0 && (mxy - mny) > 0;
        g_proj  [cam*N + n] = make_float4(fx1, fy1, fx2, fy2);
        g_parea [cam*N + n] = (fx2 - fx1) * (fy2 - fy1);
        g_validf[cam*N + n] = valid ? 1.0f : 0.0f;
        if (valid) {
            int pos = atomicAdd(&g_vcount[cam], 1);   // order irrelevant
            g_vlist[cam*N + pos] = n;
        }
    } else if (w < NCAM * N + M) {
        int m = w - NCAM * N;
        int l = dlab[m], b = dbat[m], c = dcam[m];
        if (b == 0 && l >= 1 && l <= NCLS && c >= 0 && c < NCAM) {
            int bkt = c * NCLS + l - 1;
            int r = atomicAdd(&g_brank[bkt], 1);
            if (r < CAP) {               // memory-safety clamp
                float4 db = __ldg((const float4*)dbox + m);
                g_sbox[bkt * CAP + r] = db;
                g_sas [bkt * CAP + r] =
                    make_float2((db.z - db.x) * (db.w - db.y), dsc[m]);
            }
        }
    } else if (w < NCAM * N + M + NCLS * NMAX) {
        g_probs[w - NCAM * N - M] = 0.0f;
    }
}

// ============================================================================
// K2: main IoU class accumulation (oversubscribed: 592 blocks x 256)
// ============================================================================
__global__ void k2_iou(int N) {
    const int gtid = blockIdx.x * blockDim.x + threadIdx.x;
    const int T    = gridDim.x * blockDim.x;

    __shared__ int s_cnt[NBKT];
    __shared__ int s_vbase[NCAM + 1];
    __shared__ int s_SL;

    if (threadIdx.x < NBKT) {
        int c = g_brank[threadIdx.x];
        s_cnt[threadIdx.x] = c < CAP ? c : CAP;
    }
    __syncthreads();
    if (threadIdx.x == 0) {
        int p = 0;
        #pragma unroll
        for (int c = 0; c < NCAM; c++) { s_vbase[c] = p; p += g_vcount[c]; }
        s_vbase[NCAM] = p;
        int vt = p > 0 ? p : 1;
        int sl = T / vt;
        if (sl < 1) sl = 1;
        if (sl > MAXSL) sl = MAXSL;
        s_SL = sl;
    }
    __syncthreads();

    const int SL   = s_SL;
    const int vtot = s_vbase[NCAM];
    const int W    = vtot * SL;
    for (int w = gtid; w < W; w += T) {
        int sl = w / vtot;            // consecutive threads -> consecutive pairs
        int p  = w - sl * vtot;
        int cam = 0;
        while (p >= s_vbase[cam + 1]) cam++;
        int i  = p - s_vbase[cam];
        int n  = g_vlist[cam*N + i];

        float4 pb = g_proj [cam*N + n];
        float  pa = g_parea[cam*N + n];

        #pragma unroll
        for (int cls = 0; cls < NCLS; cls++) {
            int bkt  = cam*NCLS + cls;
            int len  = s_cnt[bkt];
            int base = bkt * CAP;
            int lo = base + (len * sl)       / SL;
            int hi = base + (len * (sl + 1)) / SL;
            float a = 0.0f;
            for (int m = lo; m < hi; m++) {
                float4 db  = g_sbox[m];
                float2 as2 = g_sas[m];
                float lx = fmaxf(db.x, pb.x);
                float ly = fmaxf(db.y, pb.y);
                float rx = fminf(db.z, pb.z);
                float ry = fminf(db.w, pb.w);
                float wx = fmaxf(rx - lx, 0.0f);
                float wy = fmaxf(ry - ly, 0.0f);
                float inter = wx * wy;
                float uni   = as2.x + pa - inter;
                float iou   = __fdividef(inter, uni);
                a = fmaf(iou, as2.y, a);
            }
            if (a != 0.0f) atomicAdd(&g_probs[cls * NMAX + n], a);
        }
    }
}

// ============================================================================
// K3: finalize + counter reset
// ============================================================================
__global__ void k3_final(float* __restrict__ out, int N) {
    int n = blockIdx.x * blockDim.x + threadIdx.x;
    if (n < N) {
        float vs = 0.0f;
        #pragma unroll
        for (int cam = 0; cam < NCAM; cam++) vs += g_validf[cam*N + n];
        float denom = 1e-5f + vs;
        float best = __fdiv_rn(g_probs[n], denom);
        int bi = 0;
        #pragma unroll
        for (int c = 1; c < NCLS; c++) {
            float mv = __fdiv_rn(g_probs[c * NMAX + n], denom);
            if (mv > best) { best = mv; bi = c; }
        }
        out[n]     = (float)(bi + 1);  // pred_labels
        out[N + n] = best;             // pred_scores
    }
    // restore replay-carried counters for the next graph replay
    if (n < NBKT) g_brank[n] = 0;
    if (n < NCAM) g_vcount[n] = 0;
}

// ============================================================================
extern "C" void kernel_launch(void* const* d_in, const int* in_sizes, int n_in,
                              void* d_out, int out_size) {
    const float* boxes = (const float*)d_in[0];
    const float* iam   = (const float*)d_in[1];
    const float* lam   = (const float*)d_in[2];
    const float* l2i   = (const float*)d_in[3];
    const float* dbox  = (const float*)d_in[4];
    const int*   dlab  = (const int*)  d_in[5];
    const float* dsc   = (const float*)d_in[6];
    const int*   dbat  = (const int*)  d_in[7];
    const int*   dcam  = (const int*)  d_in[8];
    int N = in_sizes[0] / 7;
    int M = in_sizes[4] / 4;
    if (N > NMAX) N = NMAX;
    if (M > MMAX) M = MMAX;
    float* out = (float*)d_out;

    int tot1 = NCAM * N + M + NCLS * NMAX;
    k1_prep<<<(tot1 + 255) / 256, 256>>>(boxes, iam, lam, l2i, dbox,
                                         dlab, dsc, dbat, dcam, N, M);
    k2_iou <<<592, 256>>>(N);
    k3_final<<<(N + 255) / 256, 256>>>(out, N);
}